// round 1
// baseline (speedup 1.0000x reference)
#include <cuda_runtime.h>
#include <cuda_bf16.h>
#include <cstdint>

// Problem dims (fixed by the reference)
#define H_DIM   1024
#define I_DIM   2048
#define I2_DIM  4096   // 2*I
#define N_DIM   16
#define P_DIM   33     // 2N+1
#define KCONV   4
#define BATCH   2
#define SEQ     2048
#define M_DIM   4096   // BATCH*SEQ

// Scratch (device globals: allocation-free, graph-capturable)
__device__ float g_xz[(size_t)M_DIM * I2_DIM];   // 64 MB: [m][2I] = x @ W_in^T
__device__ float g_yz[(size_t)M_DIM * I_DIM];    // 32 MB: gated SSM output
__device__ float g_Aneg[I_DIM * N_DIM];          // A = -exp(A_log)

// ---------------------------------------------------------------------------
// Kernel 0: A = -exp(A_log)
// ---------------------------------------------------------------------------
__global__ void precompute_A_kernel(const float* __restrict__ A_log) {
    int idx = blockIdx.x * blockDim.x + threadIdx.x;
    if (idx < I_DIM * N_DIM) g_Aneg[idx] = -expf(A_log[idx]);
}

// ---------------------------------------------------------------------------
// SGEMM: C[m,n] = sum_k A[m,k] * B[n,k]   (both K-major / row-major, B transposed)
// BM=BN=128, BK=16, 256 threads, 8x8 microtile. All dims divisible.
// ---------------------------------------------------------------------------
#define BM 128
#define BN 128
#define BKD 16

__global__ __launch_bounds__(256, 2)
void sgemm_abT_kernel(const float* __restrict__ A, const float* __restrict__ B,
                      float* __restrict__ C, int M, int N, int K) {
    __shared__ float As[BKD][BM];
    __shared__ float Bs[BKD][BN];

    const int tid = threadIdx.x;            // 0..255
    const int tr  = tid >> 4;               // 0..15
    const int tc  = tid & 15;               // 0..15
    const int m0  = blockIdx.y * BM;
    const int n0  = blockIdx.x * BN;

    const float* Ag = A + (size_t)m0 * K;
    const float* Bg = B + (size_t)n0 * K;

    float acc[8][8];
#pragma unroll
    for (int i = 0; i < 8; i++)
#pragma unroll
        for (int j = 0; j < 8; j++) acc[i][j] = 0.f;

    for (int k0 = 0; k0 < K; k0 += BKD) {
        // Load 128x16 A tile and 128x16 B tile (512 float4 each; 2 per thread)
#pragma unroll
        for (int jj = 0; jj < 2; jj++) {
            int f   = tid + 256 * jj;       // 0..511
            int row = f >> 2;               // 0..127
            int kq  = f & 3;                // 0..3
            float4 va = *(const float4*)(Ag + (size_t)row * K + k0 + kq * 4);
            As[kq * 4 + 0][row] = va.x;
            As[kq * 4 + 1][row] = va.y;
            As[kq * 4 + 2][row] = va.z;
            As[kq * 4 + 3][row] = va.w;
            float4 vb = *(const float4*)(Bg + (size_t)row * K + k0 + kq * 4);
            Bs[kq * 4 + 0][row] = vb.x;
            Bs[kq * 4 + 1][row] = vb.y;
            Bs[kq * 4 + 2][row] = vb.z;
            Bs[kq * 4 + 3][row] = vb.w;
        }
        __syncthreads();

#pragma unroll
        for (int k = 0; k < BKD; k++) {
            float ra[8], rb[8];
#pragma unroll
            for (int i = 0; i < 8; i++) ra[i] = As[k][tr * 8 + i];
#pragma unroll
            for (int j = 0; j < 8; j++) rb[j] = Bs[k][tc * 8 + j];
#pragma unroll
            for (int i = 0; i < 8; i++)
#pragma unroll
                for (int j = 0; j < 8; j++) acc[i][j] = fmaf(ra[i], rb[j], acc[i][j]);
        }
        __syncthreads();
    }

#pragma unroll
    for (int i = 0; i < 8; i++) {
        float* Crow = C + (size_t)(m0 + tr * 8 + i) * N + n0 + tc * 8;
#pragma unroll
        for (int j = 0; j < 8; j += 4) {
            *(float4*)(Crow + j) =
                make_float4(acc[i][j], acc[i][j + 1], acc[i][j + 2], acc[i][j + 3]);
        }
    }
}

// ---------------------------------------------------------------------------
// Middle kernel: one block per (b,s) row.
//  conv(K=4 causal, depthwise) + silu -> xc (smem)
//  xproj[33] = xc . W_x[p]            (warp-per-p dots)
//  delta = softplus(xproj[0]); BC[n] = xproj[1+n]*xproj[17+n]
//  yz[m,i] = xc[i]*(D[i] + sum_n BC[n]*exp(delta*A[i,n])) * silu(z[m,i])
// ---------------------------------------------------------------------------
__global__ __launch_bounds__(256)
void middle_kernel(const float* __restrict__ conv_w,  // [I,1,K]
                   const float* __restrict__ W_x,     // [33, I]
                   const float* __restrict__ D) {     // [I]
    const int m = blockIdx.x;           // 0..M-1
    const int s = m & (SEQ - 1);        // pos in sequence (SEQ power of 2)

    __shared__ float xc_s[I_DIM];       // 8 KB
    __shared__ float proj_s[P_DIM + 7];
    __shared__ float bc_s[N_DIM];
    __shared__ float delta_s;

    const float* xz_row = g_xz + (size_t)m * I2_DIM;

    // conv + silu
    for (int i = threadIdx.x; i < I_DIM; i += blockDim.x) {
        float acc = 0.f;
        const float* w = conv_w + i * KCONV;
#pragma unroll
        for (int k = 0; k < KCONV; k++) {
            int sp = s - (KCONV - 1) + k;
            if (sp >= 0)
                acc = fmaf(g_xz[(size_t)(m - (KCONV - 1) + k) * I2_DIM + i], w[k], acc);
        }
        float sg = 1.f / (1.f + __expf(-acc));
        xc_s[i] = acc * sg;
    }
    __syncthreads();

    // 33 projection dots: warp w handles p = w, w+8, ...
    const int warp = threadIdx.x >> 5;
    const int lane = threadIdx.x & 31;
    for (int p = warp; p < P_DIM; p += 8) {
        float acc = 0.f;
        const float* w = W_x + (size_t)p * I_DIM;
        for (int i = lane; i < I_DIM; i += 32) acc = fmaf(xc_s[i], w[i], acc);
#pragma unroll
        for (int off = 16; off > 0; off >>= 1)
            acc += __shfl_down_sync(0xffffffffu, acc, off);
        if (lane == 0) proj_s[p] = acc;
    }
    __syncthreads();

    if (threadIdx.x < N_DIM)
        bc_s[threadIdx.x] = proj_s[1 + threadIdx.x] * proj_s[1 + N_DIM + threadIdx.x];
    if (threadIdx.x == 0) {
        float v = proj_s[0];
        delta_s = (v > 20.f) ? v : log1pf(expf(v));   // stable softplus
    }
    __syncthreads();

    const float delta = delta_s;
    for (int i = threadIdx.x; i < I_DIM; i += blockDim.x) {
        float acc = D[i];
        const float* a = g_Aneg + i * N_DIM;
#pragma unroll
        for (int n = 0; n < N_DIM; n++)
            acc = fmaf(bc_s[n], __expf(delta * a[n]), acc);
        float y  = xc_s[i] * acc;
        float zv = xz_row[I_DIM + i];
        float gz = zv / (1.f + __expf(-zv));          // silu(z)
        g_yz[(size_t)m * I_DIM + i] = y * gz;
    }
}

// ---------------------------------------------------------------------------
// Launcher
// ---------------------------------------------------------------------------
extern "C" void kernel_launch(void* const* d_in, const int* in_sizes, int n_in,
                              void* d_out, int out_size) {
    const float* x      = (const float*)d_in[0];   // [B,S,H]
    const float* W_in   = (const float*)d_in[1];   // [2I, H]
    const float* conv_w = (const float*)d_in[2];   // [I,1,K]
    const float* W_x    = (const float*)d_in[3];   // [33, I]
    const float* A_log  = (const float*)d_in[4];   // [I, N]
    const float* D      = (const float*)d_in[5];   // [I]
    const float* W_out  = (const float*)d_in[6];   // [H, I]
    float* out = (float*)d_out;                    // [B,S,H]

    float* xz_ptr = nullptr;
    float* yz_ptr = nullptr;
    cudaGetSymbolAddress((void**)&xz_ptr, g_xz);
    cudaGetSymbolAddress((void**)&yz_ptr, g_yz);

    // 0) A = -exp(A_log)
    precompute_A_kernel<<<(I_DIM * N_DIM + 255) / 256, 256>>>(A_log);

    // 1) xz = x @ W_in^T   : M=4096, N=4096, K=1024
    {
        dim3 grid(I2_DIM / BN, M_DIM / BM);
        sgemm_abT_kernel<<<grid, 256>>>(x, W_in, xz_ptr, M_DIM, I2_DIM, H_DIM);
    }

    // 2) conv + silu + proj + ssm + gate -> yz
    middle_kernel<<<M_DIM, 256>>>(conv_w, W_x, D);

    // 3) out = yz @ W_out^T : M=4096, N=1024, K=2048
    {
        dim3 grid(H_DIM / BN, M_DIM / BM);
        sgemm_abT_kernel<<<grid, 256>>>(yz_ptr, W_out, out, M_DIM, H_DIM, I_DIM);
    }
}

// round 3
// speedup vs baseline: 2.0829x; 2.0829x over previous
#include <cuda_runtime.h>
#include <cuda_bf16.h>
#include <cstdint>

// Problem dims (fixed by the reference)
#define H_DIM   1024
#define I_DIM   2048
#define I2_DIM  4096   // 2*I
#define N_DIM   16
#define P_DIM   33     // 2N+1
#define KCONV   4
#define BATCH   2
#define SEQ     2048
#define M_DIM   4096   // BATCH*SEQ

// Scratch (device globals: allocation-free, graph-capturable)
__device__ float g_xz[(size_t)M_DIM * I2_DIM];   // 64 MB
__device__ float g_yz[(size_t)M_DIM * I_DIM];    // 32 MB
__device__ float g_Aneg[I_DIM * N_DIM];

__device__ __forceinline__ uint32_t rna_tf32(float f) {
    uint32_t o;
    asm("cvt.rna.tf32.f32 %0, %1;" : "=r"(o) : "f"(f));
    return o;
}

// ===========================================================================
// TF32 GEMM via warp-level mma.sync (m16n8k8), C[m,n] = sum_k A[m,k]*B[n,k].
// Tile 128x128x32. 256 threads = 8 warps in 2(m) x 4(n); warp tile 64x32.
// Smem rows padded to 36 floats: conflict-free STS.128 tile stores AND
// conflict-free fragment LDS (bank = 4*row + k mod 32 covers all 32 banks).
// Double-buffered smem with register prefetch of the next K-chunk.
// ===========================================================================
#define BMT 128
#define BNT 128
#define BKT 32
#define PADW 36
#define BUF_FLOATS (BMT * PADW)      // 4608 floats per operand buffer

__global__ __launch_bounds__(256, 2)
void gemm_tf32_mma(const float* __restrict__ A, const float* __restrict__ B,
                   float* __restrict__ C, int M, int N, int K) {
    extern __shared__ float sm[];
    float* As = sm;                          // [2][BUF_FLOATS]
    float* Bs = sm + 2 * BUF_FLOATS;         // [2][BUF_FLOATS]

    const int tid  = threadIdx.x;
    const int lane = tid & 31;
    const int wid  = tid >> 5;
    const int wm   = wid >> 2;               // 0..1
    const int wn   = wid & 3;                // 0..3
    const int gid  = lane >> 2;              // 0..7
    const int tig  = lane & 3;               // 0..3
    const int m0   = blockIdx.y * BMT;
    const int n0   = blockIdx.x * BNT;

    const float* Ag = A + (size_t)m0 * K;
    const float* Bg = B + (size_t)n0 * K;

    // Per-thread tile-load coordinates: 1024 float4 per operand, 4 per thread.
    int lm[4], lk[4];
#pragma unroll
    for (int j = 0; j < 4; j++) {
        int f = tid + 256 * j;
        lm[j] = f >> 3;                      // row 0..127
        lk[j] = (f & 7) * 4;                 // k offset 0,4,..,28
    }

    float acc[4][4][4];
#pragma unroll
    for (int i = 0; i < 4; i++)
#pragma unroll
        for (int j = 0; j < 4; j++)
#pragma unroll
            for (int q = 0; q < 4; q++) acc[i][j][q] = 0.f;

    const int nchunk = K / BKT;
    uint4 ar[4], br[4];

    // ---- load chunk 0 into regs, store to buffer 0 ----
#pragma unroll
    for (int j = 0; j < 4; j++) {
        float4 va = *(const float4*)(Ag + (size_t)lm[j] * K + lk[j]);
        ar[j] = make_uint4(rna_tf32(va.x), rna_tf32(va.y), rna_tf32(va.z), rna_tf32(va.w));
        float4 vb = *(const float4*)(Bg + (size_t)lm[j] * K + lk[j]);
        br[j] = make_uint4(rna_tf32(vb.x), rna_tf32(vb.y), rna_tf32(vb.z), rna_tf32(vb.w));
    }
#pragma unroll
    for (int j = 0; j < 4; j++) {
        *(uint4*)(As + lm[j] * PADW + lk[j]) = ar[j];
        *(uint4*)(Bs + lm[j] * PADW + lk[j]) = br[j];
    }
    __syncthreads();

    for (int c = 0; c < nchunk; c++) {
        const int buf = c & 1;

        // Prefetch next chunk into registers (overlaps with MMA below).
        if (c + 1 < nchunk) {
            const int k0 = (c + 1) * BKT;
#pragma unroll
            for (int j = 0; j < 4; j++) {
                float4 va = *(const float4*)(Ag + (size_t)lm[j] * K + k0 + lk[j]);
                ar[j] = make_uint4(rna_tf32(va.x), rna_tf32(va.y), rna_tf32(va.z), rna_tf32(va.w));
                float4 vb = *(const float4*)(Bg + (size_t)lm[j] * K + k0 + lk[j]);
                br[j] = make_uint4(rna_tf32(vb.x), rna_tf32(vb.y), rna_tf32(vb.z), rna_tf32(vb.w));
            }
        }

        // MMA over this chunk: 4 k-steps of 8.
        const uint32_t* ab = (const uint32_t*)(As + buf * BUF_FLOATS) + (wm * 64 + gid) * PADW + tig;
        const uint32_t* bb = (const uint32_t*)(Bs + buf * BUF_FLOATS) + (wn * 32 + gid) * PADW + tig;
#pragma unroll
        for (int ks = 0; ks < 4; ks++) {
            const int k0 = ks * 8;
            uint32_t af[4][4];
#pragma unroll
            for (int i = 0; i < 4; i++) {
                af[i][0] = ab[(i * 16 + 0) * PADW + k0];
                af[i][1] = ab[(i * 16 + 8) * PADW + k0];
                af[i][2] = ab[(i * 16 + 0) * PADW + k0 + 4];
                af[i][3] = ab[(i * 16 + 8) * PADW + k0 + 4];
            }
            uint32_t bf[4][2];
#pragma unroll
            for (int j = 0; j < 4; j++) {
                bf[j][0] = bb[(j * 8) * PADW + k0];
                bf[j][1] = bb[(j * 8) * PADW + k0 + 4];
            }
#pragma unroll
            for (int i = 0; i < 4; i++)
#pragma unroll
                for (int j = 0; j < 4; j++) {
                    asm volatile(
                        "mma.sync.aligned.m16n8k8.row.col.f32.tf32.tf32.f32 "
                        "{%0,%1,%2,%3}, {%4,%5,%6,%7}, {%8,%9}, {%0,%1,%2,%3};"
                        : "+f"(acc[i][j][0]), "+f"(acc[i][j][1]),
                          "+f"(acc[i][j][2]), "+f"(acc[i][j][3])
                        : "r"(af[i][0]), "r"(af[i][1]), "r"(af[i][2]), "r"(af[i][3]),
                          "r"(bf[j][0]), "r"(bf[j][1]));
                }
        }

        if (c + 1 < nchunk) {
            __syncthreads();   // all warps done reading buf^1 (chunk c-1)
            const int nb = 1 - buf;
#pragma unroll
            for (int j = 0; j < 4; j++) {
                *(uint4*)(As + nb * BUF_FLOATS + lm[j] * PADW + lk[j]) = ar[j];
                *(uint4*)(Bs + nb * BUF_FLOATS + lm[j] * PADW + lk[j]) = br[j];
            }
            __syncthreads();
        }
    }

    // Epilogue: direct STG.64 per c-fragment pair.
#pragma unroll
    for (int i = 0; i < 4; i++) {
        const int r0 = m0 + wm * 64 + i * 16 + gid;
#pragma unroll
        for (int j = 0; j < 4; j++) {
            const int cc = n0 + wn * 32 + j * 8 + 2 * tig;
            *(float2*)(C + (size_t)r0 * N + cc)       = make_float2(acc[i][j][0], acc[i][j][1]);
            *(float2*)(C + (size_t)(r0 + 8) * N + cc) = make_float2(acc[i][j][2], acc[i][j][3]);
        }
    }
}

// ---------------------------------------------------------------------------
// Kernel 0: A = -exp(A_log)
// ---------------------------------------------------------------------------
__global__ void precompute_A_kernel(const float* __restrict__ A_log) {
    int idx = blockIdx.x * blockDim.x + threadIdx.x;
    if (idx < I_DIM * N_DIM) g_Aneg[idx] = -expf(A_log[idx]);
}

// ---------------------------------------------------------------------------
// Middle kernel: one block per (b,s) row (unchanged; optimize next round).
// ---------------------------------------------------------------------------
__global__ __launch_bounds__(256)
void middle_kernel(const float* __restrict__ conv_w,
                   const float* __restrict__ W_x,
                   const float* __restrict__ D) {
    const int m = blockIdx.x;
    const int s = m & (SEQ - 1);

    __shared__ float xc_s[I_DIM];
    __shared__ float proj_s[P_DIM + 7];
    __shared__ float bc_s[N_DIM];
    __shared__ float delta_s;

    const float* xz_row = g_xz + (size_t)m * I2_DIM;

    for (int i = threadIdx.x; i < I_DIM; i += blockDim.x) {
        float acc = 0.f;
        const float* w = conv_w + i * KCONV;
#pragma unroll
        for (int k = 0; k < KCONV; k++) {
            int sp = s - (KCONV - 1) + k;
            if (sp >= 0)
                acc = fmaf(g_xz[(size_t)(m - (KCONV - 1) + k) * I2_DIM + i], w[k], acc);
        }
        float sg = 1.f / (1.f + __expf(-acc));
        xc_s[i] = acc * sg;
    }
    __syncthreads();

    const int warp = threadIdx.x >> 5;
    const int lane = threadIdx.x & 31;
    for (int p = warp; p < P_DIM; p += 8) {
        float acc = 0.f;
        const float* w = W_x + (size_t)p * I_DIM;
        for (int i = lane; i < I_DIM; i += 32) acc = fmaf(xc_s[i], w[i], acc);
#pragma unroll
        for (int off = 16; off > 0; off >>= 1)
            acc += __shfl_down_sync(0xffffffffu, acc, off);
        if (lane == 0) proj_s[p] = acc;
    }
    __syncthreads();

    if (threadIdx.x < N_DIM)
        bc_s[threadIdx.x] = proj_s[1 + threadIdx.x] * proj_s[1 + N_DIM + threadIdx.x];
    if (threadIdx.x == 0) {
        float v = proj_s[0];
        delta_s = (v > 20.f) ? v : log1pf(expf(v));
    }
    __syncthreads();

    const float delta = delta_s;
    for (int i = threadIdx.x; i < I_DIM; i += blockDim.x) {
        float acc = D[i];
        const float* a = g_Aneg + i * N_DIM;
#pragma unroll
        for (int n = 0; n < N_DIM; n++)
            acc = fmaf(bc_s[n], __expf(delta * a[n]), acc);
        float y  = xc_s[i] * acc;
        float zv = xz_row[I_DIM + i];
        float gz = zv / (1.f + __expf(-zv));
        g_yz[(size_t)m * I_DIM + i] = y * gz;
    }
}

// ---------------------------------------------------------------------------
// Launcher
// ---------------------------------------------------------------------------
#define GEMM_SMEM_BYTES (4 * BUF_FLOATS * (int)sizeof(float))   // 73728 B

extern "C" void kernel_launch(void* const* d_in, const int* in_sizes, int n_in,
                              void* d_out, int out_size) {
    const float* x      = (const float*)d_in[0];
    const float* W_in   = (const float*)d_in[1];
    const float* conv_w = (const float*)d_in[2];
    const float* W_x    = (const float*)d_in[3];
    const float* A_log  = (const float*)d_in[4];
    const float* D      = (const float*)d_in[5];
    const float* W_out  = (const float*)d_in[6];
    float* out = (float*)d_out;

    float* xz_ptr = nullptr;
    float* yz_ptr = nullptr;
    cudaGetSymbolAddress((void**)&xz_ptr, g_xz);
    cudaGetSymbolAddress((void**)&yz_ptr, g_yz);

    cudaFuncSetAttribute(gemm_tf32_mma,
                         cudaFuncAttributeMaxDynamicSharedMemorySize, GEMM_SMEM_BYTES);

    precompute_A_kernel<<<(I_DIM * N_DIM + 255) / 256, 256>>>(A_log);

    // 1) xz = x @ W_in^T : M=4096, N=4096, K=1024
    {
        dim3 grid(I2_DIM / BNT, M_DIM / BMT);
        gemm_tf32_mma<<<grid, 256, GEMM_SMEM_BYTES>>>(x, W_in, xz_ptr, M_DIM, I2_DIM, H_DIM);
    }

    // 2) middle
    middle_kernel<<<M_DIM, 256>>>(conv_w, W_x, D);

    // 3) out = yz @ W_out^T : M=4096, N=1024, K=2048
    {
        dim3 grid(H_DIM / BNT, M_DIM / BMT);
        gemm_tf32_mma<<<grid, 256, GEMM_SMEM_BYTES>>>(yz_ptr, W_out, out, M_DIM, H_DIM, I_DIM);
    }
}

// round 4
// speedup vs baseline: 2.4931x; 1.1969x over previous
#include <cuda_runtime.h>
#include <cuda_bf16.h>
#include <cstdint>

// Problem dims (fixed by the reference)
#define H_DIM   1024
#define I_DIM   2048
#define I2_DIM  4096   // 2*I
#define N_DIM   16
#define P_DIM   33     // 2N+1
#define KCONV   4
#define BATCH   2
#define SEQ     2048
#define M_DIM   4096   // BATCH*SEQ

// Scratch (device globals: allocation-free, graph-capturable)
__device__ float g_xz[(size_t)M_DIM * I2_DIM];    // 64 MB (GEMM1 out, fp32)
__device__ float g_yz[(size_t)M_DIM * I_DIM];     // 32 MB (middle out, tf32-rounded)
__device__ float g_Aneg[I_DIM * N_DIM];
__device__ float g_xr [(size_t)M_DIM * H_DIM];    // 16 MB (x, tf32-rounded)
__device__ float g_wir[(size_t)I2_DIM * H_DIM];   // 16 MB (W_in, tf32-rounded)
__device__ float g_wor[(size_t)H_DIM * I_DIM];    //  8 MB (W_out, tf32-rounded)

__device__ __forceinline__ uint32_t rna_tf32(float f) {
    uint32_t o;
    asm("cvt.rna.tf32.f32 %0, %1;" : "=r"(o) : "f"(f));
    return o;
}
__device__ __forceinline__ uint32_t smem_u32(const void* p) {
    uint32_t a;
    asm("{ .reg .u64 t; cvta.to.shared.u64 t, %1; cvt.u32.u64 %0, t; }" : "=r"(a) : "l"(p));
    return a;
}
__device__ __forceinline__ void cp_async16(uint32_t dst, const void* src) {
    asm volatile("cp.async.cg.shared.global [%0], [%1], 16;" :: "r"(dst), "l"(src));
}

// ---------------------------------------------------------------------------
// Elementwise tf32 rounding pass (float4 vectorized; counts divisible by 4)
// ---------------------------------------------------------------------------
__global__ void round_tf32_kernel(const float* __restrict__ in, float* __restrict__ out,
                                  int n4) {
    int i = blockIdx.x * blockDim.x + threadIdx.x;
    if (i < n4) {
        float4 v = ((const float4*)in)[i];
        uint4 u = make_uint4(rna_tf32(v.x), rna_tf32(v.y), rna_tf32(v.z), rna_tf32(v.w));
        ((uint4*)out)[i] = u;
    }
}

// ===========================================================================
// TF32 GEMM via mma.sync m16n8k8, 3-stage cp.async pipeline.
// C[m,n] = sum_k A[m,k]*B[n,k]; A,B pre-rounded to tf32 in gmem.
// Tile 128x128x32, 256 threads (8 warps 2x4, warp tile 64x32).
// Smem rows padded to 36 floats (144B, 16B-aligned for cp.async).
// ===========================================================================
#define BMT 128
#define BNT 128
#define BKT 32
#define PADW 36
#define BUF_FLOATS (BMT * PADW)              // 4608 floats
#define BUF_BYTES  (BUF_FLOATS * 4)          // 18432 B
#define STAGES 3
#define GEMM_SMEM_BYTES (STAGES * 2 * BUF_BYTES)   // 110592 B

__global__ __launch_bounds__(256, 2)
void gemm_tf32_mma(const float* __restrict__ A, const float* __restrict__ B,
                   float* __restrict__ C, int M, int N, int K) {
    extern __shared__ float sm[];
    float* As = sm;                           // [STAGES][BUF_FLOATS]
    float* Bs = sm + STAGES * BUF_FLOATS;     // [STAGES][BUF_FLOATS]
    const uint32_t sA = smem_u32(As);
    const uint32_t sB = smem_u32(Bs);

    const int tid  = threadIdx.x;
    const int lane = tid & 31;
    const int wid  = tid >> 5;
    const int wm   = wid >> 2;                // 0..1
    const int wn   = wid & 3;                 // 0..3
    const int gid  = lane >> 2;               // 0..7
    const int tig  = lane & 3;                // 0..3
    const int m0   = blockIdx.y * BMT;
    const int n0   = blockIdx.x * BNT;

    const float* Ag = A + (size_t)m0 * K;
    const float* Bg = B + (size_t)n0 * K;

    // Per-thread copy coords: 1024 x 16B per operand tile, 4 per thread.
    int lm[4], lk[4];
    uint32_t soff[4];
#pragma unroll
    for (int j = 0; j < 4; j++) {
        int f = tid + 256 * j;
        lm[j] = f >> 3;
        lk[j] = (f & 7) * 4;
        soff[j] = (uint32_t)(lm[j] * PADW + lk[j]) * 4u;
    }

    float acc[4][4][4];
#pragma unroll
    for (int i = 0; i < 4; i++)
#pragma unroll
        for (int j = 0; j < 4; j++)
#pragma unroll
            for (int q = 0; q < 4; q++) acc[i][j][q] = 0.f;

    const int nchunk = K / BKT;

    // Prologue: issue stages 0..STAGES-2
#pragma unroll
    for (int s = 0; s < STAGES - 1; s++) {
        const int k0 = s * BKT;
        const uint32_t sa = sA + s * BUF_BYTES;
        const uint32_t sb = sB + s * BUF_BYTES;
#pragma unroll
        for (int j = 0; j < 4; j++) {
            cp_async16(sa + soff[j], Ag + (size_t)lm[j] * K + k0 + lk[j]);
            cp_async16(sb + soff[j], Bg + (size_t)lm[j] * K + k0 + lk[j]);
        }
        asm volatile("cp.async.commit_group;");
    }

    for (int c = 0; c < nchunk; c++) {
        asm volatile("cp.async.wait_group 1;");
        __syncthreads();

        const int buf = c % STAGES;
        const uint32_t* ab = (const uint32_t*)(As + buf * BUF_FLOATS) + (wm * 64 + gid) * PADW + tig;
        const uint32_t* bb = (const uint32_t*)(Bs + buf * BUF_FLOATS) + (wn * 32 + gid) * PADW + tig;
#pragma unroll
        for (int ks = 0; ks < 4; ks++) {
            const int k0 = ks * 8;
            uint32_t af[4][4];
#pragma unroll
            for (int i = 0; i < 4; i++) {
                af[i][0] = ab[(i * 16 + 0) * PADW + k0];
                af[i][1] = ab[(i * 16 + 8) * PADW + k0];
                af[i][2] = ab[(i * 16 + 0) * PADW + k0 + 4];
                af[i][3] = ab[(i * 16 + 8) * PADW + k0 + 4];
            }
            uint32_t bf[4][2];
#pragma unroll
            for (int j = 0; j < 4; j++) {
                bf[j][0] = bb[(j * 8) * PADW + k0];
                bf[j][1] = bb[(j * 8) * PADW + k0 + 4];
            }
#pragma unroll
            for (int i = 0; i < 4; i++)
#pragma unroll
                for (int j = 0; j < 4; j++) {
                    asm volatile(
                        "mma.sync.aligned.m16n8k8.row.col.f32.tf32.tf32.f32 "
                        "{%0,%1,%2,%3}, {%4,%5,%6,%7}, {%8,%9}, {%0,%1,%2,%3};"
                        : "+f"(acc[i][j][0]), "+f"(acc[i][j][1]),
                          "+f"(acc[i][j][2]), "+f"(acc[i][j][3])
                        : "r"(af[i][0]), "r"(af[i][1]), "r"(af[i][2]), "r"(af[i][3]),
                          "r"(bf[j][0]), "r"(bf[j][1]));
                }
        }

        // Issue copy for chunk c+STAGES-1 into the buffer read at iter c-1.
        const int cn = c + STAGES - 1;
        if (cn < nchunk) {
            const int k0 = cn * BKT;
            const int nb = cn % STAGES;
            const uint32_t sa = sA + nb * BUF_BYTES;
            const uint32_t sb = sB + nb * BUF_BYTES;
#pragma unroll
            for (int j = 0; j < 4; j++) {
                cp_async16(sa + soff[j], Ag + (size_t)lm[j] * K + k0 + lk[j]);
                cp_async16(sb + soff[j], Bg + (size_t)lm[j] * K + k0 + lk[j]);
            }
        }
        asm volatile("cp.async.commit_group;");   // (possibly empty) keeps group math uniform
    }

    // Epilogue: direct stores.
#pragma unroll
    for (int i = 0; i < 4; i++) {
        const int r0 = m0 + wm * 64 + i * 16 + gid;
#pragma unroll
        for (int j = 0; j < 4; j++) {
            const int cc = n0 + wn * 32 + j * 8 + 2 * tig;
            *(float2*)(C + (size_t)r0 * N + cc)       = make_float2(acc[i][j][0], acc[i][j][1]);
            *(float2*)(C + (size_t)(r0 + 8) * N + cc) = make_float2(acc[i][j][2], acc[i][j][3]);
        }
    }
}

// ---------------------------------------------------------------------------
// Kernel 0: A = -exp(A_log)
// ---------------------------------------------------------------------------
__global__ void precompute_A_kernel(const float* __restrict__ A_log) {
    int idx = blockIdx.x * blockDim.x + threadIdx.x;
    if (idx < I_DIM * N_DIM) g_Aneg[idx] = -expf(A_log[idx]);
}

// ---------------------------------------------------------------------------
// Middle kernel: one block per (b,s) row. Output rounded to tf32 (consumed
// only by GEMM2, which now expects pre-rounded operands).
// ---------------------------------------------------------------------------
__global__ __launch_bounds__(256)
void middle_kernel(const float* __restrict__ conv_w,
                   const float* __restrict__ W_x,
                   const float* __restrict__ D) {
    const int m = blockIdx.x;
    const int s = m & (SEQ - 1);

    __shared__ float xc_s[I_DIM];
    __shared__ float proj_s[P_DIM + 7];
    __shared__ float bc_s[N_DIM];
    __shared__ float delta_s;

    const float* xz_row = g_xz + (size_t)m * I2_DIM;

    for (int i = threadIdx.x; i < I_DIM; i += blockDim.x) {
        float acc = 0.f;
        const float* w = conv_w + i * KCONV;
#pragma unroll
        for (int k = 0; k < KCONV; k++) {
            int sp = s - (KCONV - 1) + k;
            if (sp >= 0)
                acc = fmaf(g_xz[(size_t)(m - (KCONV - 1) + k) * I2_DIM + i], w[k], acc);
        }
        float sg = 1.f / (1.f + __expf(-acc));
        xc_s[i] = acc * sg;
    }
    __syncthreads();

    const int warp = threadIdx.x >> 5;
    const int lane = threadIdx.x & 31;
    for (int p = warp; p < P_DIM; p += 8) {
        float acc = 0.f;
        const float* w = W_x + (size_t)p * I_DIM;
        for (int i = lane; i < I_DIM; i += 32) acc = fmaf(xc_s[i], w[i], acc);
#pragma unroll
        for (int off = 16; off > 0; off >>= 1)
            acc += __shfl_down_sync(0xffffffffu, acc, off);
        if (lane == 0) proj_s[p] = acc;
    }
    __syncthreads();

    if (threadIdx.x < N_DIM)
        bc_s[threadIdx.x] = proj_s[1 + threadIdx.x] * proj_s[1 + N_DIM + threadIdx.x];
    if (threadIdx.x == 0) {
        float v = proj_s[0];
        delta_s = (v > 20.f) ? v : log1pf(expf(v));
    }
    __syncthreads();

    const float delta = delta_s;
    for (int i = threadIdx.x; i < I_DIM; i += blockDim.x) {
        float acc = D[i];
        const float* a = g_Aneg + i * N_DIM;
#pragma unroll
        for (int n = 0; n < N_DIM; n++)
            acc = fmaf(bc_s[n], __expf(delta * a[n]), acc);
        float y  = xc_s[i] * acc;
        float zv = xz_row[I_DIM + i];
        float gz = zv / (1.f + __expf(-zv));
        g_yz[(size_t)m * I_DIM + i] = __uint_as_float(rna_tf32(y * gz));
    }
}

// ---------------------------------------------------------------------------
// Launcher
// ---------------------------------------------------------------------------
extern "C" void kernel_launch(void* const* d_in, const int* in_sizes, int n_in,
                              void* d_out, int out_size) {
    const float* x      = (const float*)d_in[0];
    const float* W_in   = (const float*)d_in[1];
    const float* conv_w = (const float*)d_in[2];
    const float* W_x    = (const float*)d_in[3];
    const float* A_log  = (const float*)d_in[4];
    const float* D      = (const float*)d_in[5];
    const float* W_out  = (const float*)d_in[6];
    float* out = (float*)d_out;

    float *xz_ptr, *yz_ptr, *xr_ptr, *wir_ptr, *wor_ptr;
    cudaGetSymbolAddress((void**)&xz_ptr,  g_xz);
    cudaGetSymbolAddress((void**)&yz_ptr,  g_yz);
    cudaGetSymbolAddress((void**)&xr_ptr,  g_xr);
    cudaGetSymbolAddress((void**)&wir_ptr, g_wir);
    cudaGetSymbolAddress((void**)&wor_ptr, g_wor);

    cudaFuncSetAttribute(gemm_tf32_mma,
                         cudaFuncAttributeMaxDynamicSharedMemorySize, GEMM_SMEM_BYTES);

    precompute_A_kernel<<<(I_DIM * N_DIM + 255) / 256, 256>>>(A_log);

    // Pre-round GEMM operands to tf32 (RNA) in gmem.
    {
        int n4x = (M_DIM * H_DIM) / 4;
        round_tf32_kernel<<<(n4x + 255) / 256, 256>>>(x, xr_ptr, n4x);
        int n4w = (I2_DIM * H_DIM) / 4;
        round_tf32_kernel<<<(n4w + 255) / 256, 256>>>(W_in, wir_ptr, n4w);
        int n4o = (H_DIM * I_DIM) / 4;
        round_tf32_kernel<<<(n4o + 255) / 256, 256>>>(W_out, wor_ptr, n4o);
    }

    // 1) xz = x @ W_in^T : M=4096, N=4096, K=1024
    {
        dim3 grid(I2_DIM / BNT, M_DIM / BMT);
        gemm_tf32_mma<<<grid, 256, GEMM_SMEM_BYTES>>>(xr_ptr, wir_ptr, xz_ptr,
                                                      M_DIM, I2_DIM, H_DIM);
    }

    // 2) middle (writes tf32-rounded yz)
    middle_kernel<<<M_DIM, 256>>>(conv_w, W_x, D);

    // 3) out = yz @ W_out^T : M=4096, N=1024, K=2048
    {
        dim3 grid(H_DIM / BNT, M_DIM / BMT);
        gemm_tf32_mma<<<grid, 256, GEMM_SMEM_BYTES>>>(yz_ptr, wor_ptr, out,
                                                      M_DIM, H_DIM, I_DIM);
    }
}

// round 5
// speedup vs baseline: 2.8957x; 1.1615x over previous
#include <cuda_runtime.h>
#include <cuda_bf16.h>
#include <cstdint>

// Problem dims (fixed by the reference)
#define H_DIM   1024
#define I_DIM   2048
#define I2_DIM  4096   // 2*I
#define N_DIM   16
#define P_DIM   33     // 2N+1
#define KCONV   4
#define BATCH   2
#define SEQ     2048
#define M_DIM   4096   // BATCH*SEQ

// Scratch (device globals: allocation-free, graph-capturable)
__device__ float g_xz[(size_t)M_DIM * I2_DIM];    // 64 MB (GEMM1 out, fp32)
__device__ float g_yz[(size_t)M_DIM * I_DIM];     // 32 MB (ssm out, tf32-rounded)
__device__ float g_xc[(size_t)M_DIM * I_DIM];     // 32 MB (conv+silu out)
__device__ float g_proj[(size_t)M_DIM * P_DIM];   // 540 KB (xproj)
__device__ float g_Aneg[I_DIM * N_DIM];
__device__ float g_xr [(size_t)M_DIM * H_DIM];    // 16 MB (x, tf32-rounded)
__device__ float g_wir[(size_t)I2_DIM * H_DIM];   // 16 MB (W_in, tf32-rounded)
__device__ float g_wor[(size_t)H_DIM * I_DIM];    //  8 MB (W_out, tf32-rounded)

__device__ __forceinline__ uint32_t rna_tf32(float f) {
    uint32_t o;
    asm("cvt.rna.tf32.f32 %0, %1;" : "=r"(o) : "f"(f));
    return o;
}
__device__ __forceinline__ uint32_t smem_u32(const void* p) {
    uint32_t a;
    asm("{ .reg .u64 t; cvta.to.shared.u64 t, %1; cvt.u32.u64 %0, t; }" : "=r"(a) : "l"(p));
    return a;
}
__device__ __forceinline__ void cp_async16(uint32_t dst, const void* src) {
    asm volatile("cp.async.cg.shared.global [%0], [%1], 16;" :: "r"(dst), "l"(src));
}

// ---------------------------------------------------------------------------
// Elementwise tf32 rounding pass
// ---------------------------------------------------------------------------
__global__ void round_tf32_kernel(const float* __restrict__ in, float* __restrict__ out,
                                  int n4) {
    int i = blockIdx.x * blockDim.x + threadIdx.x;
    if (i < n4) {
        float4 v = ((const float4*)in)[i];
        ((uint4*)out)[i] = make_uint4(rna_tf32(v.x), rna_tf32(v.y), rna_tf32(v.z), rna_tf32(v.w));
    }
}

// ===========================================================================
// TF32 GEMM via mma.sync m16n8k8, 3-stage cp.async pipeline (unchanged R4).
// ===========================================================================
#define BMT 128
#define BNT 128
#define BKT 32
#define PADW 36
#define BUF_FLOATS (BMT * PADW)
#define BUF_BYTES  (BUF_FLOATS * 4)
#define STAGES 3
#define GEMM_SMEM_BYTES (STAGES * 2 * BUF_BYTES)

__global__ __launch_bounds__(256, 2)
void gemm_tf32_mma(const float* __restrict__ A, const float* __restrict__ B,
                   float* __restrict__ C, int M, int N, int K) {
    extern __shared__ float sm[];
    float* As = sm;
    float* Bs = sm + STAGES * BUF_FLOATS;
    const uint32_t sA = smem_u32(As);
    const uint32_t sB = smem_u32(Bs);

    const int tid  = threadIdx.x;
    const int lane = tid & 31;
    const int wid  = tid >> 5;
    const int wm   = wid >> 2;
    const int wn   = wid & 3;
    const int gid  = lane >> 2;
    const int tig  = lane & 3;
    const int m0   = blockIdx.y * BMT;
    const int n0   = blockIdx.x * BNT;

    const float* Ag = A + (size_t)m0 * K;
    const float* Bg = B + (size_t)n0 * K;

    int lm[4], lk[4];
    uint32_t soff[4];
#pragma unroll
    for (int j = 0; j < 4; j++) {
        int f = tid + 256 * j;
        lm[j] = f >> 3;
        lk[j] = (f & 7) * 4;
        soff[j] = (uint32_t)(lm[j] * PADW + lk[j]) * 4u;
    }

    float acc[4][4][4];
#pragma unroll
    for (int i = 0; i < 4; i++)
#pragma unroll
        for (int j = 0; j < 4; j++)
#pragma unroll
            for (int q = 0; q < 4; q++) acc[i][j][q] = 0.f;

    const int nchunk = K / BKT;

#pragma unroll
    for (int s = 0; s < STAGES - 1; s++) {
        const int k0 = s * BKT;
        const uint32_t sa = sA + s * BUF_BYTES;
        const uint32_t sb = sB + s * BUF_BYTES;
#pragma unroll
        for (int j = 0; j < 4; j++) {
            cp_async16(sa + soff[j], Ag + (size_t)lm[j] * K + k0 + lk[j]);
            cp_async16(sb + soff[j], Bg + (size_t)lm[j] * K + k0 + lk[j]);
        }
        asm volatile("cp.async.commit_group;");
    }

    for (int c = 0; c < nchunk; c++) {
        asm volatile("cp.async.wait_group 1;");
        __syncthreads();

        const int buf = c % STAGES;
        const uint32_t* ab = (const uint32_t*)(As + buf * BUF_FLOATS) + (wm * 64 + gid) * PADW + tig;
        const uint32_t* bb = (const uint32_t*)(Bs + buf * BUF_FLOATS) + (wn * 32 + gid) * PADW + tig;
#pragma unroll
        for (int ks = 0; ks < 4; ks++) {
            const int k0 = ks * 8;
            uint32_t af[4][4];
#pragma unroll
            for (int i = 0; i < 4; i++) {
                af[i][0] = ab[(i * 16 + 0) * PADW + k0];
                af[i][1] = ab[(i * 16 + 8) * PADW + k0];
                af[i][2] = ab[(i * 16 + 0) * PADW + k0 + 4];
                af[i][3] = ab[(i * 16 + 8) * PADW + k0 + 4];
            }
            uint32_t bf[4][2];
#pragma unroll
            for (int j = 0; j < 4; j++) {
                bf[j][0] = bb[(j * 8) * PADW + k0];
                bf[j][1] = bb[(j * 8) * PADW + k0 + 4];
            }
#pragma unroll
            for (int i = 0; i < 4; i++)
#pragma unroll
                for (int j = 0; j < 4; j++) {
                    asm volatile(
                        "mma.sync.aligned.m16n8k8.row.col.f32.tf32.tf32.f32 "
                        "{%0,%1,%2,%3}, {%4,%5,%6,%7}, {%8,%9}, {%0,%1,%2,%3};"
                        : "+f"(acc[i][j][0]), "+f"(acc[i][j][1]),
                          "+f"(acc[i][j][2]), "+f"(acc[i][j][3])
                        : "r"(af[i][0]), "r"(af[i][1]), "r"(af[i][2]), "r"(af[i][3]),
                          "r"(bf[j][0]), "r"(bf[j][1]));
                }
        }

        const int cn = c + STAGES - 1;
        if (cn < nchunk) {
            const int k0 = cn * BKT;
            const int nb = cn % STAGES;
            const uint32_t sa = sA + nb * BUF_BYTES;
            const uint32_t sb = sB + nb * BUF_BYTES;
#pragma unroll
            for (int j = 0; j < 4; j++) {
                cp_async16(sa + soff[j], Ag + (size_t)lm[j] * K + k0 + lk[j]);
                cp_async16(sb + soff[j], Bg + (size_t)lm[j] * K + k0 + lk[j]);
            }
        }
        asm volatile("cp.async.commit_group;");
    }

#pragma unroll
    for (int i = 0; i < 4; i++) {
        const int r0 = m0 + wm * 64 + i * 16 + gid;
#pragma unroll
        for (int j = 0; j < 4; j++) {
            const int cc = n0 + wn * 32 + j * 8 + 2 * tig;
            *(float2*)(C + (size_t)r0 * N + cc)       = make_float2(acc[i][j][0], acc[i][j][1]);
            *(float2*)(C + (size_t)(r0 + 8) * N + cc) = make_float2(acc[i][j][2], acc[i][j][3]);
        }
    }
}

// ---------------------------------------------------------------------------
// A = -exp(A_log)
// ---------------------------------------------------------------------------
__global__ void precompute_A_kernel(const float* __restrict__ A_log) {
    int idx = blockIdx.x * blockDim.x + threadIdx.x;
    if (idx < I_DIM * N_DIM) g_Aneg[idx] = -expf(A_log[idx]);
}

// ---------------------------------------------------------------------------
// Middle stage 1: depthwise conv (K=4 causal) + silu.
// Each thread: 4 consecutive m rows x 4 consecutive channels (sliding window).
// ---------------------------------------------------------------------------
__global__ __launch_bounds__(256)
void conv_silu_kernel(const float* __restrict__ conv_w) {
    const int idx = blockIdx.x * blockDim.x + threadIdx.x;   // 0..524287
    const int ig  = idx & (I_DIM / 4 - 1);                   // channel group
    const int mg  = idx >> 9;                                // m group (4 rows)
    const int m0  = mg * 4;
    const int s0  = m0 & (SEQ - 1);
    const int i   = ig * 4;

    const float4 w0 = ((const float4*)conv_w)[i + 0];
    const float4 w1 = ((const float4*)conv_w)[i + 1];
    const float4 w2 = ((const float4*)conv_w)[i + 2];
    const float4 w3 = ((const float4*)conv_w)[i + 3];

    float4 r[7];
#pragma unroll
    for (int t = 0; t < 7; t++) {
        int sp = s0 - 3 + t;
        if (sp >= 0 && t < 7)  // t<7 always; guard is on sp
            r[t] = ((const float4*)g_xz)[(size_t)(m0 - 3 + t) * (I2_DIM / 4) + ig];
        else
            r[t] = make_float4(0.f, 0.f, 0.f, 0.f);
    }
    // t==3..6 are rows m0..m0+3 (sp = s0..s0+3 >= 0 always)
#pragma unroll
    for (int o = 0; o < 3; o++) {
        int sp = s0 - 3 + o;
        if (sp < 0) r[o] = make_float4(0.f, 0.f, 0.f, 0.f);
    }

#pragma unroll
    for (int o = 0; o < 4; o++) {
        float4 acc;
        acc.x = r[o].x * w0.x + r[o+1].x * w0.y + r[o+2].x * w0.z + r[o+3].x * w0.w;
        acc.y = r[o].y * w1.x + r[o+1].y * w1.y + r[o+2].y * w1.z + r[o+3].y * w1.w;
        acc.z = r[o].z * w2.x + r[o+1].z * w2.y + r[o+2].z * w2.z + r[o+3].z * w2.w;
        acc.w = r[o].w * w3.x + r[o+1].w * w3.y + r[o+2].w * w3.z + r[o+3].w * w3.w;
        acc.x = acc.x / (1.f + __expf(-acc.x));
        acc.y = acc.y / (1.f + __expf(-acc.y));
        acc.z = acc.z / (1.f + __expf(-acc.z));
        acc.w = acc.w / (1.f + __expf(-acc.w));
        ((float4*)g_xc)[(size_t)(m0 + o) * (I_DIM / 4) + ig] = acc;
    }
}

// ---------------------------------------------------------------------------
// Middle stage 2: xproj[m][p] = sum_i xc[m][i] * W_x[p][i]  (p = 0..32)
// 256 threads = 8 warps; each warp handles 2 rows. W_x staged in smem in
// K-chunks of 1024 (33*1024 floats = 132 KB), read once per block (16 rows).
// ---------------------------------------------------------------------------
#define PROJ_ROWS 16
#define PROJ_KC   1024
#define PROJ_SMEM (P_DIM * PROJ_KC * 4)   // 135168 B

__global__ __launch_bounds__(256)
void proj_kernel(const float* __restrict__ W_x) {
    extern __shared__ float wxs[];        // [33][PROJ_KC]
    const int tid  = threadIdx.x;
    const int lane = tid & 31;
    const int wid  = tid >> 5;
    const int rb   = blockIdx.x * PROJ_ROWS;
    const int r0   = rb + wid * 2;

    const float* x0 = g_xc + (size_t)r0 * I_DIM;
    const float* x1 = g_xc + (size_t)(r0 + 1) * I_DIM;

    float acc0[P_DIM], acc1[P_DIM];
#pragma unroll
    for (int p = 0; p < P_DIM; p++) { acc0[p] = 0.f; acc1[p] = 0.f; }

    for (int k0 = 0; k0 < I_DIM; k0 += PROJ_KC) {
        __syncthreads();
        // stage W_x chunk: 33 * 256 float4
        for (int f = tid; f < P_DIM * (PROJ_KC / 4); f += 256) {
            int p  = f / (PROJ_KC / 4);
            int kq = f % (PROJ_KC / 4);
            ((float4*)wxs)[p * (PROJ_KC / 4) + kq] =
                ((const float4*)(W_x + (size_t)p * I_DIM + k0))[kq];
        }
        __syncthreads();

        for (int kk = lane; kk < PROJ_KC; kk += 32) {
            float xv0 = x0[k0 + kk];
            float xv1 = x1[k0 + kk];
#pragma unroll
            for (int p = 0; p < P_DIM; p++) {
                float w = wxs[p * PROJ_KC + kk];
                acc0[p] = fmaf(xv0, w, acc0[p]);
                acc1[p] = fmaf(xv1, w, acc1[p]);
            }
        }
    }

    // warp reductions, lane 0 writes
#pragma unroll
    for (int p = 0; p < P_DIM; p++) {
        float v0 = acc0[p], v1 = acc1[p];
#pragma unroll
        for (int off = 16; off > 0; off >>= 1) {
            v0 += __shfl_down_sync(0xffffffffu, v0, off);
            v1 += __shfl_down_sync(0xffffffffu, v1, off);
        }
        if (lane == 0) {
            g_proj[(size_t)r0 * P_DIM + p]       = v0;
            g_proj[(size_t)(r0 + 1) * P_DIM + p] = v1;
        }
    }
}

// ---------------------------------------------------------------------------
// Middle stage 3: ssm + gate. Block = 32 m-rows; A[i,:] loaded once per
// (thread, i) and reused across the 32 m's. Writes tf32-rounded yz.
// ---------------------------------------------------------------------------
#define SSM_MT 32

__global__ __launch_bounds__(256)
void ssm_kernel(const float* __restrict__ D) {
    const int rb  = blockIdx.x * SSM_MT;
    const int tid = threadIdx.x;

    __shared__ float delta_s[SSM_MT];
    __shared__ float bc_s[SSM_MT][N_DIM];

    if (tid < SSM_MT) {
        const float* pr = g_proj + (size_t)(rb + tid) * P_DIM;
        float v = pr[0];
        delta_s[tid] = (v > 20.f) ? v : log1pf(__expf(v));
#pragma unroll
        for (int n = 0; n < N_DIM; n++)
            bc_s[tid][n] = pr[1 + n] * pr[1 + N_DIM + n];
    }
    __syncthreads();

    for (int ii = tid; ii < I_DIM; ii += 256) {
        float a[N_DIM];
        *(float4*)&a[0]  = *(const float4*)(g_Aneg + ii * N_DIM + 0);
        *(float4*)&a[4]  = *(const float4*)(g_Aneg + ii * N_DIM + 4);
        *(float4*)&a[8]  = *(const float4*)(g_Aneg + ii * N_DIM + 8);
        *(float4*)&a[12] = *(const float4*)(g_Aneg + ii * N_DIM + 12);
        const float d = D[ii];

#pragma unroll 4
        for (int mm = 0; mm < SSM_MT; mm++) {
            const int m = rb + mm;
            const float delta = delta_s[mm];
            float acc = d;
#pragma unroll
            for (int n = 0; n < N_DIM; n++)
                acc = fmaf(bc_s[mm][n], __expf(delta * a[n]), acc);
            float xcv = g_xc[(size_t)m * I_DIM + ii];
            float zv  = g_xz[(size_t)m * I2_DIM + I_DIM + ii];
            float gz  = zv / (1.f + __expf(-zv));
            g_yz[(size_t)m * I_DIM + ii] = __uint_as_float(rna_tf32(xcv * acc * gz));
        }
    }
}

// ---------------------------------------------------------------------------
// Launcher
// ---------------------------------------------------------------------------
extern "C" void kernel_launch(void* const* d_in, const int* in_sizes, int n_in,
                              void* d_out, int out_size) {
    const float* x      = (const float*)d_in[0];
    const float* W_in   = (const float*)d_in[1];
    const float* conv_w = (const float*)d_in[2];
    const float* W_x    = (const float*)d_in[3];
    const float* A_log  = (const float*)d_in[4];
    const float* D      = (const float*)d_in[5];
    const float* W_out  = (const float*)d_in[6];
    float* out = (float*)d_out;

    float *xz_ptr, *yz_ptr, *xr_ptr, *wir_ptr, *wor_ptr;
    cudaGetSymbolAddress((void**)&xz_ptr,  g_xz);
    cudaGetSymbolAddress((void**)&yz_ptr,  g_yz);
    cudaGetSymbolAddress((void**)&xr_ptr,  g_xr);
    cudaGetSymbolAddress((void**)&wir_ptr, g_wir);
    cudaGetSymbolAddress((void**)&wor_ptr, g_wor);

    cudaFuncSetAttribute(gemm_tf32_mma,
                         cudaFuncAttributeMaxDynamicSharedMemorySize, GEMM_SMEM_BYTES);
    cudaFuncSetAttribute(proj_kernel,
                         cudaFuncAttributeMaxDynamicSharedMemorySize, PROJ_SMEM);

    precompute_A_kernel<<<(I_DIM * N_DIM + 255) / 256, 256>>>(A_log);

    // Pre-round GEMM operands to tf32 (RNA).
    {
        int n4x = (M_DIM * H_DIM) / 4;
        round_tf32_kernel<<<(n4x + 255) / 256, 256>>>(x, xr_ptr, n4x);
        int n4w = (I2_DIM * H_DIM) / 4;
        round_tf32_kernel<<<(n4w + 255) / 256, 256>>>(W_in, wir_ptr, n4w);
        int n4o = (H_DIM * I_DIM) / 4;
        round_tf32_kernel<<<(n4o + 255) / 256, 256>>>(W_out, wor_ptr, n4o);
    }

    // 1) xz = x @ W_in^T
    {
        dim3 grid(I2_DIM / BNT, M_DIM / BMT);
        gemm_tf32_mma<<<grid, 256, GEMM_SMEM_BYTES>>>(xr_ptr, wir_ptr, xz_ptr,
                                                      M_DIM, I2_DIM, H_DIM);
    }

    // 2) middle: conv+silu -> proj -> ssm+gate
    conv_silu_kernel<<<(M_DIM / 4) * (I_DIM / 4) / 256, 256>>>(conv_w);
    proj_kernel<<<M_DIM / PROJ_ROWS, 256, PROJ_SMEM>>>(W_x);
    ssm_kernel<<<M_DIM / SSM_MT, 256>>>(D);

    // 3) out = yz @ W_out^T
    {
        dim3 grid(H_DIM / BNT, M_DIM / BMT);
        gemm_tf32_mma<<<grid, 256, GEMM_SMEM_BYTES>>>(yz_ptr, wor_ptr, out,
                                                      M_DIM, H_DIM, I_DIM);
    }
}

// round 6
// speedup vs baseline: 3.0747x; 1.0618x over previous
#include <cuda_runtime.h>
#include <cuda_bf16.h>
#include <cstdint>

// Problem dims (fixed by the reference)
#define H_DIM   1024
#define I_DIM   2048
#define I2_DIM  4096   // 2*I
#define N_DIM   16
#define P_DIM   33     // 2N+1
#define KCONV   4
#define BATCH   2
#define SEQ     2048
#define M_DIM   4096   // BATCH*SEQ

// Scratch (device globals: allocation-free, graph-capturable)
__device__ float g_xz[(size_t)M_DIM * I2_DIM];    // 64 MB (GEMM1 out, fp32)
__device__ float g_yz[(size_t)M_DIM * I_DIM];     // 32 MB (ssm out, tf32-rounded)
__device__ float g_xc[(size_t)M_DIM * I_DIM];     // 32 MB (conv+silu out)
__device__ float g_proj[(size_t)M_DIM * P_DIM];   // 540 KB (xproj)
__device__ float g_Aneg[I_DIM * N_DIM];
__device__ float g_xr [(size_t)M_DIM * H_DIM];    // 16 MB (x, tf32-rounded)
__device__ float g_wir[(size_t)I2_DIM * H_DIM];   // 16 MB (W_in, tf32-rounded)
__device__ float g_wor[(size_t)H_DIM * I_DIM];    //  8 MB (W_out, tf32-rounded)

__device__ __forceinline__ uint32_t rna_tf32(float f) {
    uint32_t o;
    asm("cvt.rna.tf32.f32 %0, %1;" : "=r"(o) : "f"(f));
    return o;
}
__device__ __forceinline__ uint32_t smem_u32(const void* p) {
    uint32_t a;
    asm("{ .reg .u64 t; cvta.to.shared.u64 t, %1; cvt.u32.u64 %0, t; }" : "=r"(a) : "l"(p));
    return a;
}
__device__ __forceinline__ void cp_async16(uint32_t dst, const void* src) {
    asm volatile("cp.async.cg.shared.global [%0], [%1], 16;" :: "r"(dst), "l"(src));
}

// ---------------------------------------------------------------------------
// Elementwise tf32 rounding pass
// ---------------------------------------------------------------------------
__global__ void round_tf32_kernel(const float* __restrict__ in, float* __restrict__ out,
                                  int n4) {
    int i = blockIdx.x * blockDim.x + threadIdx.x;
    if (i < n4) {
        float4 v = ((const float4*)in)[i];
        ((uint4*)out)[i] = make_uint4(rna_tf32(v.x), rna_tf32(v.y), rna_tf32(v.z), rna_tf32(v.w));
    }
}

// ===========================================================================
// TF32 GEMM via mma.sync m16n8k8, 3-stage cp.async pipeline.
// Block tile 128x128x32; 128 threads = 4 warps (2x2); warp tile 64x64.
// Per warp-chunk: 128 LDS / 128 MMA (was 96/64 with 8 warps) -> higher
// tensor-pipe duty per issue slot.
// ===========================================================================
#define BMT 128
#define BNT 128
#define BKT 32
#define PADW 36
#define BUF_FLOATS (BMT * PADW)
#define BUF_BYTES  (BUF_FLOATS * 4)
#define STAGES 3
#define GEMM_SMEM_BYTES (STAGES * 2 * BUF_BYTES)   // 110592 B

__global__ __launch_bounds__(128, 2)
void gemm_tf32_mma(const float* __restrict__ A, const float* __restrict__ B,
                   float* __restrict__ C, int M, int N, int K) {
    extern __shared__ float sm[];
    float* As = sm;
    float* Bs = sm + STAGES * BUF_FLOATS;
    const uint32_t sA = smem_u32(As);
    const uint32_t sB = smem_u32(Bs);

    const int tid  = threadIdx.x;
    const int lane = tid & 31;
    const int wid  = tid >> 5;                // 0..3
    const int wm   = wid >> 1;                // 0..1
    const int wn   = wid & 1;                 // 0..1
    const int gid  = lane >> 2;               // 0..7
    const int tig  = lane & 3;                // 0..3
    const int m0   = blockIdx.y * BMT;
    const int n0   = blockIdx.x * BNT;

    const float* Ag = A + (size_t)m0 * K;
    const float* Bg = B + (size_t)n0 * K;

    // Per-thread copy coords: 1024 float4 per operand tile, 8 per thread.
    int lm[8], lk[8];
    uint32_t soff[8];
#pragma unroll
    for (int j = 0; j < 8; j++) {
        int f = tid + 128 * j;                // 0..1023
        lm[j] = f >> 3;
        lk[j] = (f & 7) * 4;
        soff[j] = (uint32_t)(lm[j] * PADW + lk[j]) * 4u;
    }

    float acc[4][8][4];
#pragma unroll
    for (int i = 0; i < 4; i++)
#pragma unroll
        for (int j = 0; j < 8; j++)
#pragma unroll
            for (int q = 0; q < 4; q++) acc[i][j][q] = 0.f;

    const int nchunk = K / BKT;

#pragma unroll
    for (int s = 0; s < STAGES - 1; s++) {
        const int k0 = s * BKT;
        const uint32_t sa = sA + s * BUF_BYTES;
        const uint32_t sb = sB + s * BUF_BYTES;
#pragma unroll
        for (int j = 0; j < 8; j++) {
            cp_async16(sa + soff[j], Ag + (size_t)lm[j] * K + k0 + lk[j]);
            cp_async16(sb + soff[j], Bg + (size_t)lm[j] * K + k0 + lk[j]);
        }
        asm volatile("cp.async.commit_group;");
    }

    for (int c = 0; c < nchunk; c++) {
        asm volatile("cp.async.wait_group 1;");
        __syncthreads();

        const int buf = c % STAGES;
        const uint32_t* ab = (const uint32_t*)(As + buf * BUF_FLOATS) + (wm * 64 + gid) * PADW + tig;
        const uint32_t* bb = (const uint32_t*)(Bs + buf * BUF_FLOATS) + (wn * 64 + gid) * PADW + tig;
#pragma unroll
        for (int ks = 0; ks < 4; ks++) {
            const int k0 = ks * 8;
            uint32_t af[4][4];
#pragma unroll
            for (int i = 0; i < 4; i++) {
                af[i][0] = ab[(i * 16 + 0) * PADW + k0];
                af[i][1] = ab[(i * 16 + 8) * PADW + k0];
                af[i][2] = ab[(i * 16 + 0) * PADW + k0 + 4];
                af[i][3] = ab[(i * 16 + 8) * PADW + k0 + 4];
            }
            uint32_t bf[8][2];
#pragma unroll
            for (int j = 0; j < 8; j++) {
                bf[j][0] = bb[(j * 8) * PADW + k0];
                bf[j][1] = bb[(j * 8) * PADW + k0 + 4];
            }
#pragma unroll
            for (int i = 0; i < 4; i++)
#pragma unroll
                for (int j = 0; j < 8; j++) {
                    asm volatile(
                        "mma.sync.aligned.m16n8k8.row.col.f32.tf32.tf32.f32 "
                        "{%0,%1,%2,%3}, {%4,%5,%6,%7}, {%8,%9}, {%0,%1,%2,%3};"
                        : "+f"(acc[i][j][0]), "+f"(acc[i][j][1]),
                          "+f"(acc[i][j][2]), "+f"(acc[i][j][3])
                        : "r"(af[i][0]), "r"(af[i][1]), "r"(af[i][2]), "r"(af[i][3]),
                          "r"(bf[j][0]), "r"(bf[j][1]));
                }
        }

        const int cn = c + STAGES - 1;
        if (cn < nchunk) {
            const int k0 = cn * BKT;
            const int nb = cn % STAGES;
            const uint32_t sa = sA + nb * BUF_BYTES;
            const uint32_t sb = sB + nb * BUF_BYTES;
#pragma unroll
            for (int j = 0; j < 8; j++) {
                cp_async16(sa + soff[j], Ag + (size_t)lm[j] * K + k0 + lk[j]);
                cp_async16(sb + soff[j], Bg + (size_t)lm[j] * K + k0 + lk[j]);
            }
        }
        asm volatile("cp.async.commit_group;");
    }

    // Epilogue
#pragma unroll
    for (int i = 0; i < 4; i++) {
        const int r0 = m0 + wm * 64 + i * 16 + gid;
#pragma unroll
        for (int j = 0; j < 8; j++) {
            const int cc = n0 + wn * 64 + j * 8 + 2 * tig;
            *(float2*)(C + (size_t)r0 * N + cc)       = make_float2(acc[i][j][0], acc[i][j][1]);
            *(float2*)(C + (size_t)(r0 + 8) * N + cc) = make_float2(acc[i][j][2], acc[i][j][3]);
        }
    }
}

// ---------------------------------------------------------------------------
// A = -exp(A_log)
// ---------------------------------------------------------------------------
__global__ void precompute_A_kernel(const float* __restrict__ A_log) {
    int idx = blockIdx.x * blockDim.x + threadIdx.x;
    if (idx < I_DIM * N_DIM) g_Aneg[idx] = -expf(A_log[idx]);
}

// ---------------------------------------------------------------------------
// Middle stage 1: depthwise conv (K=4 causal) + silu (unchanged).
// ---------------------------------------------------------------------------
__global__ __launch_bounds__(256)
void conv_silu_kernel(const float* __restrict__ conv_w) {
    const int idx = blockIdx.x * blockDim.x + threadIdx.x;
    const int ig  = idx & (I_DIM / 4 - 1);
    const int mg  = idx >> 9;
    const int m0  = mg * 4;
    const int s0  = m0 & (SEQ - 1);
    const int i   = ig * 4;

    const float4 w0 = ((const float4*)conv_w)[i + 0];
    const float4 w1 = ((const float4*)conv_w)[i + 1];
    const float4 w2 = ((const float4*)conv_w)[i + 2];
    const float4 w3 = ((const float4*)conv_w)[i + 3];

    float4 r[7];
#pragma unroll
    for (int t = 0; t < 7; t++) {
        int sp = s0 - 3 + t;
        if (sp >= 0)
            r[t] = ((const float4*)g_xz)[(size_t)(m0 - 3 + t) * (I2_DIM / 4) + ig];
        else
            r[t] = make_float4(0.f, 0.f, 0.f, 0.f);
    }

#pragma unroll
    for (int o = 0; o < 4; o++) {
        float4 acc;
        acc.x = r[o].x * w0.x + r[o+1].x * w0.y + r[o+2].x * w0.z + r[o+3].x * w0.w;
        acc.y = r[o].y * w1.x + r[o+1].y * w1.y + r[o+2].y * w1.z + r[o+3].y * w1.w;
        acc.z = r[o].z * w2.x + r[o+1].z * w2.y + r[o+2].z * w2.z + r[o+3].z * w2.w;
        acc.w = r[o].w * w3.x + r[o+1].w * w3.y + r[o+2].w * w3.z + r[o+3].w * w3.w;
        acc.x = acc.x / (1.f + __expf(-acc.x));
        acc.y = acc.y / (1.f + __expf(-acc.y));
        acc.z = acc.z / (1.f + __expf(-acc.z));
        acc.w = acc.w / (1.f + __expf(-acc.w));
        ((float4*)g_xc)[(size_t)(m0 + o) * (I_DIM / 4) + ig] = acc;
    }
}

// ---------------------------------------------------------------------------
// Middle stage 2: xproj. K-chunk 512 -> 67.5 KB smem -> 2 blocks/SM.
// ---------------------------------------------------------------------------
#define PROJ_ROWS 16
#define PROJ_KC   512
#define PROJ_SMEM (P_DIM * PROJ_KC * 4)   // 67584 B

__global__ __launch_bounds__(256)
void proj_kernel(const float* __restrict__ W_x) {
    extern __shared__ float wxs[];        // [33][PROJ_KC]
    const int tid  = threadIdx.x;
    const int lane = tid & 31;
    const int wid  = tid >> 5;
    const int rb   = blockIdx.x * PROJ_ROWS;
    const int r0   = rb + wid * 2;

    const float* x0 = g_xc + (size_t)r0 * I_DIM;
    const float* x1 = g_xc + (size_t)(r0 + 1) * I_DIM;

    float acc0[P_DIM], acc1[P_DIM];
#pragma unroll
    for (int p = 0; p < P_DIM; p++) { acc0[p] = 0.f; acc1[p] = 0.f; }

    for (int k0 = 0; k0 < I_DIM; k0 += PROJ_KC) {
        __syncthreads();
        for (int f = tid; f < P_DIM * (PROJ_KC / 4); f += 256) {
            int p  = f / (PROJ_KC / 4);
            int kq = f % (PROJ_KC / 4);
            ((float4*)wxs)[p * (PROJ_KC / 4) + kq] =
                ((const float4*)(W_x + (size_t)p * I_DIM + k0))[kq];
        }
        __syncthreads();

        for (int kk = lane; kk < PROJ_KC; kk += 32) {
            float xv0 = x0[k0 + kk];
            float xv1 = x1[k0 + kk];
#pragma unroll
            for (int p = 0; p < P_DIM; p++) {
                float w = wxs[p * PROJ_KC + kk];
                acc0[p] = fmaf(xv0, w, acc0[p]);
                acc1[p] = fmaf(xv1, w, acc1[p]);
            }
        }
    }

#pragma unroll
    for (int p = 0; p < P_DIM; p++) {
        float v0 = acc0[p], v1 = acc1[p];
#pragma unroll
        for (int off = 16; off > 0; off >>= 1) {
            v0 += __shfl_down_sync(0xffffffffu, v0, off);
            v1 += __shfl_down_sync(0xffffffffu, v1, off);
        }
        if (lane == 0) {
            g_proj[(size_t)r0 * P_DIM + p]       = v0;
            g_proj[(size_t)(r0 + 1) * P_DIM + p] = v1;
        }
    }
}

// ---------------------------------------------------------------------------
// Middle stage 3: ssm + gate (unchanged).
// ---------------------------------------------------------------------------
#define SSM_MT 32

__global__ __launch_bounds__(256)
void ssm_kernel(const float* __restrict__ D) {
    const int rb  = blockIdx.x * SSM_MT;
    const int tid = threadIdx.x;

    __shared__ float delta_s[SSM_MT];
    __shared__ float bc_s[SSM_MT][N_DIM];

    if (tid < SSM_MT) {
        const float* pr = g_proj + (size_t)(rb + tid) * P_DIM;
        float v = pr[0];
        delta_s[tid] = (v > 20.f) ? v : log1pf(__expf(v));
#pragma unroll
        for (int n = 0; n < N_DIM; n++)
            bc_s[tid][n] = pr[1 + n] * pr[1 + N_DIM + n];
    }
    __syncthreads();

    for (int ii = tid; ii < I_DIM; ii += 256) {
        float a[N_DIM];
        *(float4*)&a[0]  = *(const float4*)(g_Aneg + ii * N_DIM + 0);
        *(float4*)&a[4]  = *(const float4*)(g_Aneg + ii * N_DIM + 4);
        *(float4*)&a[8]  = *(const float4*)(g_Aneg + ii * N_DIM + 8);
        *(float4*)&a[12] = *(const float4*)(g_Aneg + ii * N_DIM + 12);
        const float d = D[ii];

#pragma unroll 4
        for (int mm = 0; mm < SSM_MT; mm++) {
            const int m = rb + mm;
            const float delta = delta_s[mm];
            float acc = d;
#pragma unroll
            for (int n = 0; n < N_DIM; n++)
                acc = fmaf(bc_s[mm][n], __expf(delta * a[n]), acc);
            float xcv = g_xc[(size_t)m * I_DIM + ii];
            float zv  = g_xz[(size_t)m * I2_DIM + I_DIM + ii];
            float gz  = zv / (1.f + __expf(-zv));
            g_yz[(size_t)m * I_DIM + ii] = __uint_as_float(rna_tf32(xcv * acc * gz));
        }
    }
}

// ---------------------------------------------------------------------------
// Launcher
// ---------------------------------------------------------------------------
extern "C" void kernel_launch(void* const* d_in, const int* in_sizes, int n_in,
                              void* d_out, int out_size) {
    const float* x      = (const float*)d_in[0];
    const float* W_in   = (const float*)d_in[1];
    const float* conv_w = (const float*)d_in[2];
    const float* W_x    = (const float*)d_in[3];
    const float* A_log  = (const float*)d_in[4];
    const float* D      = (const float*)d_in[5];
    const float* W_out  = (const float*)d_in[6];
    float* out = (float*)d_out;

    float *xz_ptr, *yz_ptr, *xr_ptr, *wir_ptr, *wor_ptr;
    cudaGetSymbolAddress((void**)&xz_ptr,  g_xz);
    cudaGetSymbolAddress((void**)&yz_ptr,  g_yz);
    cudaGetSymbolAddress((void**)&xr_ptr,  g_xr);
    cudaGetSymbolAddress((void**)&wir_ptr, g_wir);
    cudaGetSymbolAddress((void**)&wor_ptr, g_wor);

    cudaFuncSetAttribute(gemm_tf32_mma,
                         cudaFuncAttributeMaxDynamicSharedMemorySize, GEMM_SMEM_BYTES);
    cudaFuncSetAttribute(proj_kernel,
                         cudaFuncAttributeMaxDynamicSharedMemorySize, PROJ_SMEM);

    precompute_A_kernel<<<(I_DIM * N_DIM + 255) / 256, 256>>>(A_log);

    {
        int n4x = (M_DIM * H_DIM) / 4;
        round_tf32_kernel<<<(n4x + 255) / 256, 256>>>(x, xr_ptr, n4x);
        int n4w = (I2_DIM * H_DIM) / 4;
        round_tf32_kernel<<<(n4w + 255) / 256, 256>>>(W_in, wir_ptr, n4w);
        int n4o = (H_DIM * I_DIM) / 4;
        round_tf32_kernel<<<(n4o + 255) / 256, 256>>>(W_out, wor_ptr, n4o);
    }

    // 1) xz = x @ W_in^T
    {
        dim3 grid(I2_DIM / BNT, M_DIM / BMT);
        gemm_tf32_mma<<<grid, 128, GEMM_SMEM_BYTES>>>(xr_ptr, wir_ptr, xz_ptr,
                                                      M_DIM, I2_DIM, H_DIM);
    }

    // 2) middle
    conv_silu_kernel<<<(M_DIM / 4) * (I_DIM / 4) / 256, 256>>>(conv_w);
    proj_kernel<<<M_DIM / PROJ_ROWS, 256, PROJ_SMEM>>>(W_x);
    ssm_kernel<<<M_DIM / SSM_MT, 256>>>(D);

    // 3) out = yz @ W_out^T
    {
        dim3 grid(H_DIM / BNT, M_DIM / BMT);
        gemm_tf32_mma<<<grid, 128, GEMM_SMEM_BYTES>>>(yz_ptr, wor_ptr, out,
                                                      M_DIM, H_DIM, I_DIM);
    }
}